// round 9
// baseline (speedup 1.0000x reference)
#include <cuda_runtime.h>
#include <math.h>

// Problem constants
#define BB 8
#define TT 768
#define DD 1024
#define HH 16
#define DHH 64
#define BT (BB*TT)          // 6144
#define N3 (3*DD)           // 3072
#define QKVN (BB*HH*TT*DHH) // 6291456

typedef unsigned long long ull;

// Scratch (device globals -- no allocation allowed)
__device__ float g_q[QKVN];
__device__ float g_k[QKVN];
__device__ float g_v[QKVN];
__device__ float g_cos[TT*DHH];
__device__ float g_sin[TT*DHH];

// ---- packed f32x2 helpers (sm_103a: FFMA2 only reachable via PTX) ----------
__device__ __forceinline__ ull pk2(float lo, float hi) {
    ull r; asm("mov.b64 %0, {%1,%2};" : "=l"(r) : "f"(lo), "f"(hi)); return r;
}
__device__ __forceinline__ void upk2(float &lo, float &hi, ull v) {
    asm("mov.b64 {%0,%1}, %2;" : "=f"(lo), "=f"(hi) : "l"(v));
}
__device__ __forceinline__ void fma2(ull &d, ull a, ull b) {
    asm("fma.rn.f32x2 %0, %1, %2, %0;" : "+l"(d) : "l"(a), "l"(b));
}
// ---- cp.async helpers -------------------------------------------------------
__device__ __forceinline__ unsigned s2u(const void* p) {
    return (unsigned)__cvta_generic_to_shared(p);
}
__device__ __forceinline__ void cp_async16(unsigned dst, const void* src) {
    asm volatile("cp.async.ca.shared.global [%0], [%1], 16;" :: "r"(dst), "l"(src));
}
__device__ __forceinline__ void cp_async_wait_all() {
    asm volatile("cp.async.wait_all;" ::: "memory");
}

// ---------------------------------------------------------------------------
// RoPE tables: cos/sin (T, DH), rotate-half convention (duplicated halves)
// ---------------------------------------------------------------------------
__global__ void build_rope_kernel() {
    int t = blockIdx.x;
    int i = threadIdx.x;               // 0..31 (frequency index)
    float e = (2.0f * (float)i) / 64.0f;
    float invf = powf(10000.0f, -e);
    float ang = (float)t * invf;
    float s, c;
    sincosf(ang, &s, &c);
    g_cos[t*DHH + i]      = c;
    g_cos[t*DHH + i + 32] = c;
    g_sin[t*DHH + i]      = s;
    g_sin[t*DHH + i + 32] = s;
}

// ---------------------------------------------------------------------------
// QKV GEMM: C[m][n] = sum_k x[m][k] * W[n][k] + b[n]
// M=6144, N=3072, K=1024.  BM=BN=128, BK=16, 256 threads, 8x8 micro-tile
// (packed as 8x4 f32x2). Double-buffered smem, padded stride 132.
// B micro-tile split into two 4-wide chunks (tCol*4 and 64+tCol*4): rb
// LDS.128 pattern is 16B-strided and tRow-independent -> 2 crossbar phases
// after dedup; ra is a 2-address broadcast -> 1 phase.  ~6 phases/k-step
// per warp vs 64 FMA-cycles: comfortably FMA-bound.
// Epilogue: bias + scatter into g_q/g_k/g_v with (B,H,T,DH) layout (no RoPE
// here; RoPE is fused into the attention tile loads).
// ---------------------------------------------------------------------------
#define LDA 132
#define STG_STRIDE (2*16*LDA)   // floats per stage (A tile + B tile)

__global__ __launch_bounds__(256, 2) void qkv_gemm_kernel(
    const float* __restrict__ x, const float* __restrict__ W,
    const float* __restrict__ bias)
{
    __shared__ float smem[2 * STG_STRIDE];   // 2 stages x (A 16x132 + B 16x132)

    const int bn = blockIdx.x;      // 0..23
    const int bm = blockIdx.y;      // 0..47
    const int tid = threadIdx.x;
    const int tRow = tid >> 4;      // 0..15
    const int tCol = tid & 15;      // 0..15

    const int lrow = tid >> 2;           // 0..63 (plus +64 second half)
    const int lc4  = (tid & 3) * 4;      // 0,4,8,12

    const float* Ap = x + (bm * 128) * DD;
    const float* Bp = W + (bn * 128) * DD;

    // acc[i][j]: rows tRow*8+i; j=0,1 -> cols tCol*4..+3 ; j=2,3 -> 64+tCol*4..+3
    ull accp[8][4];
    #pragma unroll
    for (int i = 0; i < 8; i++)
        #pragma unroll
        for (int j = 0; j < 4; j++)
            accp[i][j] = 0ULL;

    // ---- preload stage 0 ----
    {
        float* A0 = smem;
        float* B0 = smem + 16 * LDA;
        #pragma unroll
        for (int half = 0; half < 2; half++) {
            int row = lrow + half * 64;
            float4 a = *(const float4*)(Ap + row * DD + lc4);
            float4 b = *(const float4*)(Bp + row * DD + lc4);
            A0[(lc4+0)*LDA + row] = a.x; A0[(lc4+1)*LDA + row] = a.y;
            A0[(lc4+2)*LDA + row] = a.z; A0[(lc4+3)*LDA + row] = a.w;
            B0[(lc4+0)*LDA + row] = b.x; B0[(lc4+1)*LDA + row] = b.y;
            B0[(lc4+2)*LDA + row] = b.z; B0[(lc4+3)*LDA + row] = b.w;
        }
    }
    __syncthreads();

    int buf = 0;
    #pragma unroll 1
    for (int k0 = 0; k0 < DD; k0 += 16) {
        const bool more = (k0 + 16 < DD);
        float4 pa0, pa1, pb0, pb1;
        if (more) {
            pa0 = *(const float4*)(Ap + lrow * DD + (k0 + 16) + lc4);
            pa1 = *(const float4*)(Ap + (lrow + 64) * DD + (k0 + 16) + lc4);
            pb0 = *(const float4*)(Bp + lrow * DD + (k0 + 16) + lc4);
            pb1 = *(const float4*)(Bp + (lrow + 64) * DD + (k0 + 16) + lc4);
        }

        const float* A = smem + buf * STG_STRIDE;
        const float* B = A + 16 * LDA;

        #pragma unroll 8
        for (int k = 0; k < 16; k++) {
            float ra[8] __align__(16);
            float rb[8] __align__(16);
            *(float4*)&ra[0] = *(const float4*)(A + k * LDA + tRow * 8);
            *(float4*)&ra[4] = *(const float4*)(A + k * LDA + tRow * 8 + 4);
            *(float4*)&rb[0] = *(const float4*)(B + k * LDA + tCol * 4);        // cols [tCol*4, +4)
            *(float4*)&rb[4] = *(const float4*)(B + k * LDA + 64 + tCol * 4);   // cols [64+tCol*4, +4)
            const ull* rbp = (const ull*)rb;
            #pragma unroll
            for (int i = 0; i < 8; i++) {
                ull rap = pk2(ra[i], ra[i]);
                #pragma unroll
                for (int j = 0; j < 4; j++)
                    fma2(accp[i][j], rap, rbp[j]);
            }
        }

        if (more) {
            float* A1 = smem + (buf ^ 1) * STG_STRIDE;
            float* B1 = A1 + 16 * LDA;
            A1[(lc4+0)*LDA + lrow] = pa0.x; A1[(lc4+1)*LDA + lrow] = pa0.y;
            A1[(lc4+2)*LDA + lrow] = pa0.z; A1[(lc4+3)*LDA + lrow] = pa0.w;
            A1[(lc4+0)*LDA + lrow+64] = pa1.x; A1[(lc4+1)*LDA + lrow+64] = pa1.y;
            A1[(lc4+2)*LDA + lrow+64] = pa1.z; A1[(lc4+3)*LDA + lrow+64] = pa1.w;
            B1[(lc4+0)*LDA + lrow] = pb0.x; B1[(lc4+1)*LDA + lrow] = pb0.y;
            B1[(lc4+2)*LDA + lrow] = pb0.z; B1[(lc4+3)*LDA + lrow] = pb0.w;
            B1[(lc4+0)*LDA + lrow+64] = pb1.x; B1[(lc4+1)*LDA + lrow+64] = pb1.y;
            B1[(lc4+2)*LDA + lrow+64] = pb1.z; B1[(lc4+3)*LDA + lrow+64] = pb1.w;
        }
        buf ^= 1;
        __syncthreads();
    }

    // ---- epilogue: bias + scatter to (B,H,T,DH), two 4-col groups ----
    #pragma unroll
    for (int g = 0; g < 2; g++) {
        const int nb = bn * 128 + g * 64 + tCol * 4;  // 4 contiguous cols, within one head
        const int which = nb >> 10;                   // 0=q, 1=k, 2=v
        const int d0 = nb & (DD - 1);
        const int h  = d0 >> 6;
        const int dh0 = d0 & 63;                      // multiple of 4
        float* dst_base = (which == 0) ? g_q : (which == 1) ? g_k : g_v;

        float bv[4];
        #pragma unroll
        for (int j = 0; j < 4; j++) bv[j] = bias[nb + j];

        #pragma unroll
        for (int i = 0; i < 8; i++) {
            int m = bm * 128 + tRow * 8 + i;
            int b_ = m / TT;
            int t_ = m - b_ * TT;
            float* dst = dst_base + ((b_ * HH + h) * TT + t_) * DHH + dh0;
            float o[4];
            upk2(o[0], o[1], accp[i][2*g + 0]);
            upk2(o[2], o[3], accp[i][2*g + 1]);
            float4 ov;
            ov.x = o[0] + bv[0]; ov.y = o[1] + bv[1];
            ov.z = o[2] + bv[2]; ov.w = o[3] + bv[3];
            *(float4*)dst = ov;
        }
    }
}

// ---------------------------------------------------------------------------
// Retention: per (b,h), O = tril(Q K^T) V.  Q tile = 128 rows, K/V tiles = 64.
// RoPE applied on-the-fly while loading Q and K tiles.
// - 1D grid of 768 blocks ordered GLOBALLY heaviest-first (LPT wave packing).
// - K LDGs issued BEFORE the top-of-loop barrier (gmem-only, no hazard).
// - V tile via cp.async; waited just before the post-S-store barrier.
// - Final diagonal tile (sb == 2tq+1): threads whose whole 8-row fragment is
//   fully masked (row_max < col_min) skip both inner gemms exactly.
// Block: 256 threads (16x16), 8x4 micro-tile (8x2 f32x2).  96 KB smem,
// 2 CTAs/SM.  All LDS patterns conflict-free / broadcast-dedup'd.
//   Qs [t][d] 128x64   Ss [t][s] 128x64   Kts [d][s] 64x64   Vs [s][d] 64x64
// ---------------------------------------------------------------------------
__global__ __launch_bounds__(256, 2) void attn_kernel(float* __restrict__ out) {
    extern __shared__ float sm[];
    float* Qs  = sm;             // 8192 floats
    float* Ss  = sm + 8192;      // 8192
    float* Kts = sm + 16384;     // 4096
    float* Vs  = sm + 20480;     // 4096

    const int tq  = 5 - (blockIdx.x >> 7);   // all heavy blocks launch first
    const int bh  = blockIdx.x & 127;        // 0..127
    const int tid = threadIdx.x;
    const int tRow = tid >> 4;        // 0..15 -> 8 rows each
    const int tCol = tid & 15;        // 0..15 -> 4 cols each

    const float* __restrict__ qb = g_q + bh * (TT * DHH) + tq * 128 * DHH;
    const float* __restrict__ kb = g_k + bh * (TT * DHH);
    const float* __restrict__ vb = g_v + bh * (TT * DHH);

    // ---- load Q tile with fused RoPE ----
    #pragma unroll
    for (int it = 0; it < 8; it++) {
        int v = tid + it * 256;       // 0..2047
        int r = v >> 4;               // 0..127
        int c4 = (v & 15) * 4;        // 0..60
        int t = tq * 128 + r;
        float4 xq = *(const float4*)(qb + r * DHH + c4);
        float4 xp = *(const float4*)(qb + r * DHH + (c4 ^ 32));
        float4 cc = *(const float4*)(g_cos + t * DHH + c4);
        float4 ssn = *(const float4*)(g_sin + t * DHH + c4);
        float sgn = (c4 < 32) ? -1.0f : 1.0f;
        float4 o;
        o.x = xq.x * cc.x + sgn * xp.x * ssn.x;
        o.y = xq.y * cc.y + sgn * xp.y * ssn.y;
        o.z = xq.z * cc.z + sgn * xp.z * ssn.z;
        o.w = xq.w * cc.w + sgn * xp.w * ssn.w;
        *(float4*)&Qs[r * 64 + c4] = o;
    }

    ull accp[8][2];
    #pragma unroll
    for (int i = 0; i < 8; i++) { accp[i][0] = 0ULL; accp[i][1] = 0ULL; }

    // per-thread K-load coordinates (reused every tile)
    const int ks  = tid & 63;               // s index for K loads
    const int kd4 = (tid >> 6) * 4;         // d4 base (0,4,8,12) -> +16 per it
    const int vr  = tid >> 4;               // r index for V cp.async
    const int vc4 = (tid & 15) * 4;

    const int nsb = 2 * tq + 1;
    #pragma unroll 1
    for (int sb = 0; sb <= nsb; sb++) {
        const float* __restrict__ kt = kb + sb * 64 * DHH;
        const float* __restrict__ vt = vb + sb * 64 * DHH;

        // exact all-masked predicate: largest row index < smallest col index
        const bool all_masked = (tq * 128 + tRow * 8 + 7) < (sb * 64);

        // ---- issue K LDGs BEFORE the barrier (gmem-only; overlaps barrier) --
        float4 xk[4], xp[4];
        #pragma unroll
        for (int it = 0; it < 4; it++) {
            int d4 = kd4 + it * 16;       // 0..60
            xk[it] = *(const float4*)(kt + ks * DHH + d4);
            xp[it] = *(const float4*)(kt + ks * DHH + (d4 ^ 32));
        }

        __syncthreads();   // prev iter's smem reads (Kts/Vs/Ss) complete

        // ---- V tile: cp.async gmem->smem (waited before gemm2's barrier) ----
        #pragma unroll
        for (int it = 0; it < 4; it++) {
            int r = vr + it * 16;         // 0..63
            cp_async16(s2u(&Vs[r * 64 + vc4]), vt + r * DHH + vc4);
        }

        // ---- RoPE K -> transposed smem ----
        #pragma unroll
        for (int it = 0; it < 4; it++) {
            int d4 = kd4 + it * 16;
            int t = sb * 64 + ks;
            float4 cc = *(const float4*)(g_cos + t * DHH + d4);
            float4 ssn = *(const float4*)(g_sin + t * DHH + d4);
            float sgn = (d4 < 32) ? -1.0f : 1.0f;
            Kts[(d4+0) * 64 + ks] = xk[it].x * cc.x + sgn * xp[it].x * ssn.x;
            Kts[(d4+1) * 64 + ks] = xk[it].y * cc.y + sgn * xp[it].y * ssn.y;
            Kts[(d4+2) * 64 + ks] = xk[it].z * cc.z + sgn * xp[it].z * ssn.z;
            Kts[(d4+3) * 64 + ks] = xk[it].w * cc.w + sgn * xp[it].w * ssn.w;
        }
        __syncthreads();   // Kts visible

        // ---- gemm1: S[t][s] = sum_d Q[t][d] * K[s][d], d-chunks of 4 ----
        ull sfragp[8][2];
        #pragma unroll
        for (int i = 0; i < 8; i++) { sfragp[i][0] = 0ULL; sfragp[i][1] = 0ULL; }

        if (!all_masked) {
            #pragma unroll 2
            for (int dc = 0; dc < 64; dc += 4) {
                // hoist 4 K columns for this chunk (16 regs, reused by all 8 rows)
                ull rkp[4][2];
                #pragma unroll
                for (int dd = 0; dd < 4; dd++) {
                    float rk[4] __align__(16);
                    *(float4*)rk = *(const float4*)&Kts[(dc + dd) * 64 + tCol * 4];
                    rkp[dd][0] = ((const ull*)rk)[0];
                    rkp[dd][1] = ((const ull*)rk)[1];
                }
                // stream Q rows one LDS.128 at a time (4 live regs, not 32)
                #pragma unroll
                for (int i = 0; i < 8; i++) {
                    float q4[4] __align__(16);
                    *(float4*)q4 = *(const float4*)&Qs[(tRow * 8 + i) * 64 + dc];
                    #pragma unroll
                    for (int dd = 0; dd < 4; dd++) {
                        ull qp = pk2(q4[dd], q4[dd]);
                        fma2(sfragp[i][0], qp, rkp[dd][0]);
                        fma2(sfragp[i][1], qp, rkp[dd][1]);
                    }
                }
            }

            // ---- causal mask (only tiles overlapping the diagonal band) ----
            if (sb >= 2 * tq) {
                #pragma unroll
                for (int i = 0; i < 8; i++) {
                    int t = tq * 128 + tRow * 8 + i;
                    #pragma unroll
                    for (int j2 = 0; j2 < 2; j2++) {
                        int s0 = sb * 64 + tCol * 4 + 2 * j2;
                        float lo, hi;
                        upk2(lo, hi, sfragp[i][j2]);
                        if (s0 > t)     lo = 0.0f;
                        if (s0 + 1 > t) hi = 0.0f;
                        sfragp[i][j2] = pk2(lo, hi);
                    }
                }
            }
        }

        // ---- store S tile (zeros when fully masked) ----
        #pragma unroll
        for (int i = 0; i < 8; i++) {
            ulonglong2 sv;
            sv.x = sfragp[i][0]; sv.y = sfragp[i][1];
            *(ulonglong2*)&Ss[(tRow * 8 + i) * 64 + tCol * 4] = sv;
        }

        cp_async_wait_all();   // V arrival (per-thread), hidden behind gemm1
        __syncthreads();       // Ss + Vs visible to all

        // ---- gemm2: O[t][d] += sum_s S[t][s] * V[s][d], s-chunks of 4 ----
        // (skip exactly when this thread's S rows are known all-zero)
        if (!all_masked) {
            #pragma unroll 2
            for (int sc = 0; sc < 64; sc += 4) {
                // hoist 4 V rows for this chunk (16 regs)
                ulonglong2 rv[4];
                #pragma unroll
                for (int ss = 0; ss < 4; ss++)
                    rv[ss] = *(const ulonglong2*)&Vs[(sc + ss) * 64 + tCol * 4];
                // stream S rows one LDS.128 at a time
                #pragma unroll
                for (int i = 0; i < 8; i++) {
                    float s4[4] __align__(16);
                    *(float4*)s4 = *(const float4*)&Ss[(tRow * 8 + i) * 64 + sc];
                    #pragma unroll
                    for (int ss = 0; ss < 4; ss++) {
                        ull sp = pk2(s4[ss], s4[ss]);
                        fma2(accp[i][0], sp, rv[ss].x);
                        fma2(accp[i][1], sp, rv[ss].y);
                    }
                }
            }
        }
    }

    // ---- write output: out[b][t][h*64 + dh] ----
    const int b_ = bh >> 4;
    const int h_ = bh & 15;
    #pragma unroll
    for (int i = 0; i < 8; i++) {
        int t_ = tq * 128 + tRow * 8 + i;
        float* dst = out + (b_ * TT + t_) * DD + h_ * DHH + tCol * 4;
        float4 ov;
        upk2(ov.x, ov.y, accp[i][0]);
        upk2(ov.z, ov.w, accp[i][1]);
        *(float4*)dst = ov;
    }
}

// ---------------------------------------------------------------------------
extern "C" void kernel_launch(void* const* d_in, const int* in_sizes, int n_in,
                              void* d_out, int out_size) {
    const float* x    = (const float*)d_in[0];
    const float* W    = (const float*)d_in[1];
    const float* bias = (const float*)d_in[2];
    float* out = (float*)d_out;

    cudaFuncSetAttribute(attn_kernel,
                         cudaFuncAttributeMaxDynamicSharedMemorySize, 98304);

    build_rope_kernel<<<TT, 32>>>();
    qkv_gemm_kernel<<<dim3(N3/128, BT/128), 256>>>(x, W, bias);
    attn_kernel<<<TT/128 * BB*HH, 256, 98304>>>(out);
}

// round 14
// speedup vs baseline: 1.4898x; 1.4898x over previous
#include <cuda_runtime.h>
#include <cuda_bf16.h>
#include <math.h>
#include <stdint.h>

// Problem constants
#define BB 8
#define TT 768
#define DD 1024
#define HH 16
#define DHH 64
#define BT (BB*TT)          // 6144
#define N3 (3*DD)           // 3072
#define K3 3072             // extended K for bf16x3 split GEMM
#define QKVN (BB*HH*TT*DHH) // 6291456

typedef unsigned long long ull;

// Scratch (device globals -- no allocation allowed)
__device__ float g_q[QKVN];
__device__ float g_k[QKVN];
__device__ float g_v[QKVN];
__device__ float g_cos[TT*DHH];
__device__ float g_sin[TT*DHH];
__device__ __nv_bfloat16 g_a[BT*K3];   // A' = [x_hi | x_hi | x_lo]  (6144 x 3072)
__device__ __nv_bfloat16 g_b[N3*K3];   // B' = [w_hi | w_lo | w_hi]  (3072 x 3072)

// ---- packed f32x2 helpers (attention kernel) -------------------------------
__device__ __forceinline__ ull pk2(float lo, float hi) {
    ull r; asm("mov.b64 %0, {%1,%2};" : "=l"(r) : "f"(lo), "f"(hi)); return r;
}
__device__ __forceinline__ void upk2(float &lo, float &hi, ull v) {
    asm("mov.b64 {%0,%1}, %2;" : "=f"(lo), "=f"(hi) : "l"(v));
}
__device__ __forceinline__ void fma2(ull &d, ull a, ull b) {
    asm("fma.rn.f32x2 %0, %1, %2, %0;" : "+l"(d) : "l"(a), "l"(b));
}
// ---- cp.async helpers -------------------------------------------------------
__device__ __forceinline__ unsigned s2u(const void* p) {
    return (unsigned)__cvta_generic_to_shared(p);
}
__device__ __forceinline__ void cp_async16(unsigned dst, const void* src) {
    asm volatile("cp.async.ca.shared.global [%0], [%1], 16;" :: "r"(dst), "l"(src));
}
__device__ __forceinline__ void cp_async_commit() {
    asm volatile("cp.async.commit_group;" ::: "memory");
}
template <int N>
__device__ __forceinline__ void cp_async_wait_group() {
    asm volatile("cp.async.wait_group %0;" :: "n"(N) : "memory");
}
__device__ __forceinline__ void cp_async_wait_all() {
    asm volatile("cp.async.wait_all;" ::: "memory");
}
// ---- HMMA helpers (baseline sm_80+ PTX; no 'a'-gated features) -------------
__device__ __forceinline__ void ldmx4(unsigned &r0, unsigned &r1,
                                      unsigned &r2, unsigned &r3, unsigned addr) {
    asm volatile("ldmatrix.sync.aligned.m8n8.x4.shared.b16 {%0,%1,%2,%3}, [%4];"
                 : "=r"(r0), "=r"(r1), "=r"(r2), "=r"(r3) : "r"(addr));
}
__device__ __forceinline__ void mma16816(float* c, const unsigned* a,
                                         unsigned b0, unsigned b1) {
    asm volatile(
        "mma.sync.aligned.m16n8k16.row.col.f32.bf16.bf16.f32 "
        "{%0,%1,%2,%3}, {%4,%5,%6,%7}, {%8,%9}, {%0,%1,%2,%3};"
        : "+f"(c[0]), "+f"(c[1]), "+f"(c[2]), "+f"(c[3])
        : "r"(a[0]), "r"(a[1]), "r"(a[2]), "r"(a[3]), "r"(b0), "r"(b1));
}

// ---------------------------------------------------------------------------
// RoPE tables: cos/sin (T, DH), rotate-half convention (duplicated halves)
// ---------------------------------------------------------------------------
__global__ void build_rope_kernel() {
    int t = blockIdx.x;
    int i = threadIdx.x;               // 0..31 (frequency index)
    float e = (2.0f * (float)i) / 64.0f;
    float invf = powf(10000.0f, -e);
    float ang = (float)t * invf;
    float s, c;
    sincosf(ang, &s, &c);
    g_cos[t*DHH + i]      = c;
    g_cos[t*DHH + i + 32] = c;
    g_sin[t*DHH + i]      = s;
    g_sin[t*DHH + i + 32] = s;
}

// ---------------------------------------------------------------------------
// Split fp32 -> bf16 (hi, lo) and build extended-K operands:
//   g_a rows (6144): [x_hi(k) | x_hi(k) | x_lo(k)]   k' = 0..3071
//   g_b rows (3072): [w_hi(k) | w_lo(k) | w_hi(k)]
// so sum over K'=3072 gives hi*hi + hi*lo + lo*hi (lo*lo dropped, ~2^-18).
// ---------------------------------------------------------------------------
__global__ __launch_bounds__(256) void split_kernel(
    const float* __restrict__ x, const float* __restrict__ W)
{
    const int nx4 = (BT * DD) / 4;       // 1572864
    const int nw4 = (N3 * DD) / 4;       // 786432
    int idx = blockIdx.x * 256 + threadIdx.x;
    if (idx >= nx4 + nw4) return;

    union { __nv_bfloat16 b[4]; ull u; } Hp, Lp;

    if (idx < nx4) {
        int e = idx * 4;
        int m = e >> 10, k = e & 1023;
        float4 v = *(const float4*)(x + e);
        float vv[4] = {v.x, v.y, v.z, v.w};
        #pragma unroll
        for (int j = 0; j < 4; j++) {
            __nv_bfloat16 h = __float2bfloat16(vv[j]);
            Hp.b[j] = h;
            Lp.b[j] = __float2bfloat16(vv[j] - __bfloat162float(h));
        }
        __nv_bfloat16* row = g_a + m * K3;
        *(ull*)(row + k)        = Hp.u;
        *(ull*)(row + 1024 + k) = Hp.u;
        *(ull*)(row + 2048 + k) = Lp.u;
    } else {
        int e = (idx - nx4) * 4;
        int n = e >> 10, k = e & 1023;
        float4 v = *(const float4*)(W + e);
        float vv[4] = {v.x, v.y, v.z, v.w};
        #pragma unroll
        for (int j = 0; j < 4; j++) {
            __nv_bfloat16 h = __float2bfloat16(vv[j]);
            Hp.b[j] = h;
            Lp.b[j] = __float2bfloat16(vv[j] - __bfloat162float(h));
        }
        __nv_bfloat16* row = g_b + n * K3;
        *(ull*)(row + k)        = Hp.u;
        *(ull*)(row + 1024 + k) = Lp.u;
        *(ull*)(row + 2048 + k) = Hp.u;
    }
}

// ---------------------------------------------------------------------------
// HMMA bf16 GEMM (warp-level mma.sync; tcgen05 is 'a'-gated and unavailable
// at the harness's compute_103 PTX target).
// C[m][n] = sum_{k'} A'[m][k'] B'[n][k'] + bias[n]
// Block 128x128, BK=32, 96 chunks. 8 warps: warp (wm=wid&3, wn=wid>>2)
// computes 32(M)x64(N) via m16n8k16 atoms (2 m-atoms x 8 n-atoms).
// Smem tiles 128x32 bf16, rows padded to 40 bf16 (80B): ldmatrix 8-row
// phases hit banks r*20%32 = all-distinct -> conflict-free.
// cp.async double buffer, wait_group<1> overlap.
// Epilogue: bias + scatter to g_q/g_k/g_v, 32B-coalesced float2 stores.
// ---------------------------------------------------------------------------
#define LDT 40                    // padded row length in bf16
#define TILE_B (128*LDT*2)        // 10240 bytes per tile
#define STAGE_B (2*TILE_B)        // A + B per stage

__global__ __launch_bounds__(256, 2) void hmma_gemm_kernel(
    const float* __restrict__ bias)
{
    static __shared__ __align__(16) char smg[2 * STAGE_B];   // 40960 B

    const int tid  = threadIdx.x;
    const int wid  = tid >> 5;
    const int lane = tid & 31;
    const int wm   = wid & 3;          // m block of 32
    const int wn   = wid >> 2;         // n block of 64
    const int bn   = blockIdx.x;       // 0..23
    const int bm   = blockIdx.y;       // 0..47

    const __nv_bfloat16* __restrict__ ga = g_a + (bm * 128) * K3;
    const __nv_bfloat16* __restrict__ gb = g_b + (bn * 128) * K3;

    const unsigned sbase = s2u(smg);

    // gmem->smem mapping: thread loads rows lr, lr+64; 16B (8 bf16) at col lc
    const int lr = tid >> 2;           // 0..63
    const int lc = (tid & 3) * 8;      // bf16 col 0,8,16,24

    // per-lane ldmatrix base offsets (bytes within a stage)
    const unsigned aBase =
        ((wm*32 + (lane & 7) + ((lane >> 3) & 1) * 8) * LDT + (lane >> 4) * 8) * 2;
    const unsigned bBase =
        ((wn*64 + (lane & 7) + ((lane >> 4) & 1) * 8) * LDT + ((lane >> 3) & 1) * 8) * 2;

    float acc[2][8][4];
    #pragma unroll
    for (int i = 0; i < 2; i++)
        #pragma unroll
        for (int j = 0; j < 8; j++)
            #pragma unroll
            for (int q = 0; q < 4; q++)
                acc[i][j][q] = 0.0f;

    // ---- preload chunk 0 into stage 0 ----
    {
        unsigned sA = sbase;
        unsigned sB = sbase + TILE_B;
        cp_async16(sA + (lr*LDT + lc)*2,        ga + lr*K3 + lc);
        cp_async16(sA + ((lr+64)*LDT + lc)*2,   ga + (lr+64)*K3 + lc);
        cp_async16(sB + (lr*LDT + lc)*2,        gb + lr*K3 + lc);
        cp_async16(sB + ((lr+64)*LDT + lc)*2,   gb + (lr+64)*K3 + lc);
        cp_async_commit();
    }

    #pragma unroll 1
    for (int c = 0; c < 96; c++) {
        const int cur = c & 1;
        if (c < 95) {
            const int k0 = (c + 1) * 32;
            unsigned sA = sbase + (cur ^ 1) * STAGE_B;
            unsigned sB = sA + TILE_B;
            cp_async16(sA + (lr*LDT + lc)*2,      ga + lr*K3 + k0 + lc);
            cp_async16(sA + ((lr+64)*LDT + lc)*2, ga + (lr+64)*K3 + k0 + lc);
            cp_async16(sB + (lr*LDT + lc)*2,      gb + lr*K3 + k0 + lc);
            cp_async16(sB + ((lr+64)*LDT + lc)*2, gb + (lr+64)*K3 + k0 + lc);
            cp_async_commit();
            cp_async_wait_group<1>();   // drain current stage's group
        } else {
            cp_async_wait_group<0>();
        }
        __syncthreads();

        const unsigned sA = sbase + cur * STAGE_B;
        const unsigned sB = sA + TILE_B;

        #pragma unroll
        for (int ks = 0; ks < 32; ks += 16) {
            unsigned a[2][4];
            #pragma unroll
            for (int am = 0; am < 2; am++)
                ldmx4(a[am][0], a[am][1], a[am][2], a[am][3],
                      sA + aBase + (am*16*LDT + ks)*2);
            #pragma unroll
            for (int nb = 0; nb < 4; nb++) {
                unsigned b0, b1, b2, b3;
                ldmx4(b0, b1, b2, b3, sB + bBase + (nb*16*LDT + ks)*2);
                #pragma unroll
                for (int am = 0; am < 2; am++) {
                    mma16816(acc[am][2*nb],     a[am], b0, b1);
                    mma16816(acc[am][2*nb + 1], a[am], b2, b3);
                }
            }
        }
        __syncthreads();   // all ldmatrix done before next cp.async overwrites
    }

    // ---- epilogue: bias + scatter to (B,H,T,DH) ----
    const int b_  = bm / 6;
    const int t0  = (bm % 6) * 128 + wm * 32 + (lane >> 2);
    const int nq  = (lane & 3) * 2;

    #pragma unroll
    for (int nb = 0; nb < 8; nb++) {
        const int nbase = bn * 128 + wn * 64 + nb * 8 + nq;
        const int which = nbase >> 10;           // 0=q, 1=k, 2=v
        const int h     = (nbase & 1023) >> 6;
        const int dh    = nbase & 63;
        float* dst_base = (which == 0) ? g_q : (which == 1) ? g_k : g_v;
        const float bv0 = bias[nbase];
        const float bv1 = bias[nbase + 1];
        #pragma unroll
        for (int am = 0; am < 2; am++) {
            #pragma unroll
            for (int half = 0; half < 2; half++) {
                int t_ = t0 + am * 16 + half * 8;
                float* dst = dst_base + ((b_ * HH + h) * TT + t_) * DHH + dh;
                float2 ov;
                ov.x = acc[am][nb][2*half + 0] + bv0;
                ov.y = acc[am][nb][2*half + 1] + bv1;
                *(float2*)dst = ov;
            }
        }
    }
}

// ---------------------------------------------------------------------------
// Retention: per (b,h), O = tril(Q K^T) V.  (unchanged from passing R9)
// ---------------------------------------------------------------------------
__global__ __launch_bounds__(256, 2) void attn_kernel(float* __restrict__ out) {
    extern __shared__ float sm[];
    float* Qs  = sm;             // 8192 floats
    float* Ss  = sm + 8192;      // 8192
    float* Kts = sm + 16384;     // 4096
    float* Vs  = sm + 20480;     // 4096

    const int tq  = 5 - (blockIdx.x >> 7);   // all heavy blocks launch first
    const int bh  = blockIdx.x & 127;        // 0..127
    const int tid = threadIdx.x;
    const int tRow = tid >> 4;        // 0..15 -> 8 rows each
    const int tCol = tid & 15;        // 0..15 -> 4 cols each

    const float* __restrict__ qb = g_q + bh * (TT * DHH) + tq * 128 * DHH;
    const float* __restrict__ kb = g_k + bh * (TT * DHH);
    const float* __restrict__ vb = g_v + bh * (TT * DHH);

    #pragma unroll
    for (int it = 0; it < 8; it++) {
        int v = tid + it * 256;
        int r = v >> 4;
        int c4 = (v & 15) * 4;
        int t = tq * 128 + r;
        float4 xq = *(const float4*)(qb + r * DHH + c4);
        float4 xp = *(const float4*)(qb + r * DHH + (c4 ^ 32));
        float4 cc = *(const float4*)(g_cos + t * DHH + c4);
        float4 ssn = *(const float4*)(g_sin + t * DHH + c4);
        float sgn = (c4 < 32) ? -1.0f : 1.0f;
        float4 o;
        o.x = xq.x * cc.x + sgn * xp.x * ssn.x;
        o.y = xq.y * cc.y + sgn * xp.y * ssn.y;
        o.z = xq.z * cc.z + sgn * xp.z * ssn.z;
        o.w = xq.w * cc.w + sgn * xp.w * ssn.w;
        *(float4*)&Qs[r * 64 + c4] = o;
    }

    ull accp[8][2];
    #pragma unroll
    for (int i = 0; i < 8; i++) { accp[i][0] = 0ULL; accp[i][1] = 0ULL; }

    const int ks  = tid & 63;
    const int kd4 = (tid >> 6) * 4;
    const int vr  = tid >> 4;
    const int vc4 = (tid & 15) * 4;

    const int nsb = 2 * tq + 1;
    #pragma unroll 1
    for (int sb = 0; sb <= nsb; sb++) {
        const float* __restrict__ kt = kb + sb * 64 * DHH;
        const float* __restrict__ vt = vb + sb * 64 * DHH;
        const bool all_masked = (tq * 128 + tRow * 8 + 7) < (sb * 64);

        float4 xk[4], xp[4];
        #pragma unroll
        for (int it = 0; it < 4; it++) {
            int d4 = kd4 + it * 16;
            xk[it] = *(const float4*)(kt + ks * DHH + d4);
            xp[it] = *(const float4*)(kt + ks * DHH + (d4 ^ 32));
        }

        __syncthreads();

        #pragma unroll
        for (int it = 0; it < 4; it++) {
            int r = vr + it * 16;
            cp_async16(s2u(&Vs[r * 64 + vc4]), vt + r * DHH + vc4);
        }

        #pragma unroll
        for (int it = 0; it < 4; it++) {
            int d4 = kd4 + it * 16;
            int t = sb * 64 + ks;
            float4 cc = *(const float4*)(g_cos + t * DHH + d4);
            float4 ssn = *(const float4*)(g_sin + t * DHH + d4);
            float sgn = (d4 < 32) ? -1.0f : 1.0f;
            Kts[(d4+0) * 64 + ks] = xk[it].x * cc.x + sgn * xp[it].x * ssn.x;
            Kts[(d4+1) * 64 + ks] = xk[it].y * cc.y + sgn * xp[it].y * ssn.y;
            Kts[(d4+2) * 64 + ks] = xk[it].z * cc.z + sgn * xp[it].z * ssn.z;
            Kts[(d4+3) * 64 + ks] = xk[it].w * cc.w + sgn * xp[it].w * ssn.w;
        }
        __syncthreads();

        ull sfragp[8][2];
        #pragma unroll
        for (int i = 0; i < 8; i++) { sfragp[i][0] = 0ULL; sfragp[i][1] = 0ULL; }

        if (!all_masked) {
            #pragma unroll 2
            for (int dc = 0; dc < 64; dc += 4) {
                ull rkp[4][2];
                #pragma unroll
                for (int dd = 0; dd < 4; dd++) {
                    float rk[4] __align__(16);
                    *(float4*)rk = *(const float4*)&Kts[(dc + dd) * 64 + tCol * 4];
                    rkp[dd][0] = ((const ull*)rk)[0];
                    rkp[dd][1] = ((const ull*)rk)[1];
                }
                #pragma unroll
                for (int i = 0; i < 8; i++) {
                    float q4[4] __align__(16);
                    *(float4*)q4 = *(const float4*)&Qs[(tRow * 8 + i) * 64 + dc];
                    #pragma unroll
                    for (int dd = 0; dd < 4; dd++) {
                        ull qp = pk2(q4[dd], q4[dd]);
                        fma2(sfragp[i][0], qp, rkp[dd][0]);
                        fma2(sfragp[i][1], qp, rkp[dd][1]);
                    }
                }
            }
            if (sb >= 2 * tq) {
                #pragma unroll
                for (int i = 0; i < 8; i++) {
                    int t = tq * 128 + tRow * 8 + i;
                    #pragma unroll
                    for (int j2 = 0; j2 < 2; j2++) {
                        int s0 = sb * 64 + tCol * 4 + 2 * j2;
                        float lo, hi;
                        upk2(lo, hi, sfragp[i][j2]);
                        if (s0 > t)     lo = 0.0f;
                        if (s0 + 1 > t) hi = 0.0f;
                        sfragp[i][j2] = pk2(lo, hi);
                    }
                }
            }
        }

        #pragma unroll
        for (int i = 0; i < 8; i++) {
            ulonglong2 sv;
            sv.x = sfragp[i][0]; sv.y = sfragp[i][1];
            *(ulonglong2*)&Ss[(tRow * 8 + i) * 64 + tCol * 4] = sv;
        }

        cp_async_wait_all();
        __syncthreads();

        if (!all_masked) {
            #pragma unroll 2
            for (int sc = 0; sc < 64; sc += 4) {
                ulonglong2 rv[4];
                #pragma unroll
                for (int ss = 0; ss < 4; ss++)
                    rv[ss] = *(const ulonglong2*)&Vs[(sc + ss) * 64 + tCol * 4];
                #pragma unroll
                for (int i = 0; i < 8; i++) {
                    float s4[4] __align__(16);
                    *(float4*)s4 = *(const float4*)&Ss[(tRow * 8 + i) * 64 + sc];
                    #pragma unroll
                    for (int ss = 0; ss < 4; ss++) {
                        ull sp = pk2(s4[ss], s4[ss]);
                        fma2(accp[i][0], sp, rv[ss].x);
                        fma2(accp[i][1], sp, rv[ss].y);
                    }
                }
            }
        }
    }

    const int b_ = bh >> 4;
    const int h_ = bh & 15;
    #pragma unroll
    for (int i = 0; i < 8; i++) {
        int t_ = tq * 128 + tRow * 8 + i;
        float* dst = out + (b_ * TT + t_) * DD + h_ * DHH + tCol * 4;
        float4 ov;
        upk2(ov.x, ov.y, accp[i][0]);
        upk2(ov.z, ov.w, accp[i][1]);
        *(float4*)dst = ov;
    }
}

// ---------------------------------------------------------------------------
extern "C" void kernel_launch(void* const* d_in, const int* in_sizes, int n_in,
                              void* d_out, int out_size) {
    const float* x    = (const float*)d_in[0];
    const float* W    = (const float*)d_in[1];
    const float* bias = (const float*)d_in[2];
    float* out = (float*)d_out;

    cudaFuncSetAttribute(attn_kernel,
                         cudaFuncAttributeMaxDynamicSharedMemorySize, 98304);

    build_rope_kernel<<<TT, 32>>>();
    const int splitBlocks = ((BT*DD + N3*DD) / 4 + 255) / 256;
    split_kernel<<<splitBlocks, 256>>>(x, W);
    hmma_gemm_kernel<<<dim3(N3/128, BT/128), 256>>>(bias);
    attn_kernel<<<TT/128 * BB*HH, 256, 98304>>>(out);
}

// round 16
// speedup vs baseline: 1.7870x; 1.1994x over previous
#include <cuda_runtime.h>
#include <cuda_bf16.h>
#include <math.h>
#include <stdint.h>

// Problem constants
#define BB 8
#define TT 768
#define DD 1024
#define HH 16
#define DHH 64
#define BT (BB*TT)          // 6144
#define N3 (3*DD)           // 3072
#define K3 3072             // extended K for bf16x3 split GEMM
#define QKVN (BB*HH*TT*DHH) // 6291456

typedef unsigned long long ull;

// Scratch (device globals -- no allocation allowed)
__device__ float g_q[QKVN];
__device__ float g_k[QKVN];
__device__ float g_v[QKVN];
__device__ float g_cos[TT*DHH];
__device__ float g_sin[TT*DHH];
__device__ __nv_bfloat16 g_a[BT*K3];   // A' = [x_hi | x_hi | x_lo]  (6144 x 3072)
__device__ __nv_bfloat16 g_b[N3*K3];   // B' = [w_hi | w_lo | w_hi]  (3072 x 3072)

// ---- cp.async helpers -------------------------------------------------------
__device__ __forceinline__ unsigned s2u(const void* p) {
    return (unsigned)__cvta_generic_to_shared(p);
}
__device__ __forceinline__ void cp_async16(unsigned dst, const void* src) {
    asm volatile("cp.async.ca.shared.global [%0], [%1], 16;" :: "r"(dst), "l"(src));
}
__device__ __forceinline__ void cp_async_commit() {
    asm volatile("cp.async.commit_group;" ::: "memory");
}
template <int N>
__device__ __forceinline__ void cp_async_wait_group() {
    asm volatile("cp.async.wait_group %0;" :: "n"(N) : "memory");
}
// ---- HMMA helpers (baseline sm_80+ PTX; validated by the passing GEMM) -----
__device__ __forceinline__ void ldmx4(unsigned &r0, unsigned &r1,
                                      unsigned &r2, unsigned &r3, unsigned addr) {
    asm volatile("ldmatrix.sync.aligned.m8n8.x4.shared.b16 {%0,%1,%2,%3}, [%4];"
                 : "=r"(r0), "=r"(r1), "=r"(r2), "=r"(r3) : "r"(addr));
}
__device__ __forceinline__ void mma16816(float* c, const unsigned* a,
                                         unsigned b0, unsigned b1) {
    asm volatile(
        "mma.sync.aligned.m16n8k16.row.col.f32.bf16.bf16.f32 "
        "{%0,%1,%2,%3}, {%4,%5,%6,%7}, {%8,%9}, {%0,%1,%2,%3};"
        : "+f"(c[0]), "+f"(c[1]), "+f"(c[2]), "+f"(c[3])
        : "r"(a[0]), "r"(a[1]), "r"(a[2]), "r"(a[3]), "r"(b0), "r"(b1));
}
// pack two f32 -> bf16x2 (lo = first arg, hi = second)
__device__ __forceinline__ unsigned pkbf(float lo, float hi) {
    unsigned r;
    asm("cvt.rn.bf16x2.f32 %0, %1, %2;" : "=r"(r) : "f"(hi), "f"(lo));
    return r;
}
__device__ __forceinline__ float bfrt(float x) {      // round-trip via bf16
    return __bfloat162float(__float2bfloat16(x));
}

// ---------------------------------------------------------------------------
// RoPE tables: cos/sin (T, DH), rotate-half convention (duplicated halves)
// ---------------------------------------------------------------------------
__global__ void build_rope_kernel() {
    int t = blockIdx.x;
    int i = threadIdx.x;               // 0..31 (frequency index)
    float e = (2.0f * (float)i) / 64.0f;
    float invf = powf(10000.0f, -e);
    float ang = (float)t * invf;
    float s, c;
    sincosf(ang, &s, &c);
    g_cos[t*DHH + i]      = c;
    g_cos[t*DHH + i + 32] = c;
    g_sin[t*DHH + i]      = s;
    g_sin[t*DHH + i + 32] = s;
}

// ---------------------------------------------------------------------------
// Split fp32 -> bf16 (hi, lo) extended-K operands for the QKV GEMM.
// ---------------------------------------------------------------------------
__global__ __launch_bounds__(256) void split_kernel(
    const float* __restrict__ x, const float* __restrict__ W)
{
    const int nx4 = (BT * DD) / 4;
    const int nw4 = (N3 * DD) / 4;
    int idx = blockIdx.x * 256 + threadIdx.x;
    if (idx >= nx4 + nw4) return;

    union { __nv_bfloat16 b[4]; ull u; } Hp, Lp;

    if (idx < nx4) {
        int e = idx * 4;
        int m = e >> 10, k = e & 1023;
        float4 v = *(const float4*)(x + e);
        float vv[4] = {v.x, v.y, v.z, v.w};
        #pragma unroll
        for (int j = 0; j < 4; j++) {
            __nv_bfloat16 h = __float2bfloat16(vv[j]);
            Hp.b[j] = h;
            Lp.b[j] = __float2bfloat16(vv[j] - __bfloat162float(h));
        }
        __nv_bfloat16* row = g_a + m * K3;
        *(ull*)(row + k)        = Hp.u;
        *(ull*)(row + 1024 + k) = Hp.u;
        *(ull*)(row + 2048 + k) = Lp.u;
    } else {
        int e = (idx - nx4) * 4;
        int n = e >> 10, k = e & 1023;
        float4 v = *(const float4*)(W + e);
        float vv[4] = {v.x, v.y, v.z, v.w};
        #pragma unroll
        for (int j = 0; j < 4; j++) {
            __nv_bfloat16 h = __float2bfloat16(vv[j]);
            Hp.b[j] = h;
            Lp.b[j] = __float2bfloat16(vv[j] - __bfloat162float(h));
        }
        __nv_bfloat16* row = g_b + n * K3;
        *(ull*)(row + k)        = Hp.u;
        *(ull*)(row + 1024 + k) = Lp.u;
        *(ull*)(row + 2048 + k) = Hp.u;
    }
}

// ---------------------------------------------------------------------------
// HMMA bf16 GEMM (unchanged from passing R14).
// ---------------------------------------------------------------------------
#define LDT 40
#define TILE_B (128*LDT*2)
#define STAGE_B (2*TILE_B)

__global__ __launch_bounds__(256, 2) void hmma_gemm_kernel(
    const float* __restrict__ bias)
{
    static __shared__ __align__(16) char smg[2 * STAGE_B];

    const int tid  = threadIdx.x;
    const int wid  = tid >> 5;
    const int lane = tid & 31;
    const int wm   = wid & 3;
    const int wn   = wid >> 2;
    const int bn   = blockIdx.x;
    const int bm   = blockIdx.y;

    const __nv_bfloat16* __restrict__ ga = g_a + (bm * 128) * K3;
    const __nv_bfloat16* __restrict__ gb = g_b + (bn * 128) * K3;

    const unsigned sbase = s2u(smg);
    const int lr = tid >> 2;
    const int lc = (tid & 3) * 8;

    const unsigned aBase =
        ((wm*32 + (lane & 7) + ((lane >> 3) & 1) * 8) * LDT + (lane >> 4) * 8) * 2;
    const unsigned bBase =
        ((wn*64 + (lane & 7) + ((lane >> 4) & 1) * 8) * LDT + ((lane >> 3) & 1) * 8) * 2;

    float acc[2][8][4];
    #pragma unroll
    for (int i = 0; i < 2; i++)
        #pragma unroll
        for (int j = 0; j < 8; j++)
            #pragma unroll
            for (int q = 0; q < 4; q++)
                acc[i][j][q] = 0.0f;

    {
        unsigned sA = sbase;
        unsigned sB = sbase + TILE_B;
        cp_async16(sA + (lr*LDT + lc)*2,        ga + lr*K3 + lc);
        cp_async16(sA + ((lr+64)*LDT + lc)*2,   ga + (lr+64)*K3 + lc);
        cp_async16(sB + (lr*LDT + lc)*2,        gb + lr*K3 + lc);
        cp_async16(sB + ((lr+64)*LDT + lc)*2,   gb + (lr+64)*K3 + lc);
        cp_async_commit();
    }

    #pragma unroll 1
    for (int c = 0; c < 96; c++) {
        const int cur = c & 1;
        if (c < 95) {
            const int k0 = (c + 1) * 32;
            unsigned sA = sbase + (cur ^ 1) * STAGE_B;
            unsigned sB = sA + TILE_B;
            cp_async16(sA + (lr*LDT + lc)*2,      ga + lr*K3 + k0 + lc);
            cp_async16(sA + ((lr+64)*LDT + lc)*2, ga + (lr+64)*K3 + k0 + lc);
            cp_async16(sB + (lr*LDT + lc)*2,      gb + lr*K3 + k0 + lc);
            cp_async16(sB + ((lr+64)*LDT + lc)*2, gb + (lr+64)*K3 + k0 + lc);
            cp_async_commit();
            cp_async_wait_group<1>();
        } else {
            cp_async_wait_group<0>();
        }
        __syncthreads();

        const unsigned sA = sbase + cur * STAGE_B;
        const unsigned sB = sA + TILE_B;

        #pragma unroll
        for (int ks = 0; ks < 32; ks += 16) {
            unsigned a[2][4];
            #pragma unroll
            for (int am = 0; am < 2; am++)
                ldmx4(a[am][0], a[am][1], a[am][2], a[am][3],
                      sA + aBase + (am*16*LDT + ks)*2);
            #pragma unroll
            for (int nb = 0; nb < 4; nb++) {
                unsigned b0, b1, b2, b3;
                ldmx4(b0, b1, b2, b3, sB + bBase + (nb*16*LDT + ks)*2);
                #pragma unroll
                for (int am = 0; am < 2; am++) {
                    mma16816(acc[am][2*nb],     a[am], b0, b1);
                    mma16816(acc[am][2*nb + 1], a[am], b2, b3);
                }
            }
        }
        __syncthreads();
    }

    const int b_  = bm / 6;
    const int t0  = (bm % 6) * 128 + wm * 32 + (lane >> 2);
    const int nq  = (lane & 3) * 2;

    #pragma unroll
    for (int nb = 0; nb < 8; nb++) {
        const int nbase = bn * 128 + wn * 64 + nb * 8 + nq;
        const int which = nbase >> 10;
        const int h     = (nbase & 1023) >> 6;
        const int dh    = nbase & 63;
        float* dst_base = (which == 0) ? g_q : (which == 1) ? g_k : g_v;
        const float bv0 = bias[nbase];
        const float bv1 = bias[nbase + 1];
        #pragma unroll
        for (int am = 0; am < 2; am++) {
            #pragma unroll
            for (int half = 0; half < 2; half++) {
                int t_ = t0 + am * 16 + half * 8;
                float* dst = dst_base + ((b_ * HH + h) * TT + t_) * DHH + dh;
                float2 ov;
                ov.x = acc[am][nb][2*half + 0] + bv0;
                ov.y = acc[am][nb][2*half + 1] + bv1;
                *(float2*)dst = ov;
            }
        }
    }
}

// ---------------------------------------------------------------------------
// HMMA attention: per (b,h), O = tril(Q K^T) V via bf16x3 split mma.sync.
// Q tile 128 rows; s-tiles of 64.  8 warps: warp wid owns rows wid*16..+15,
// all 64 cols.  gemm1: S = Qhi*Khi + Qhi*Klo + Qlo*Khi (12 k-steps).
// S c-frags are masked then split hi/lo and repacked IN REGISTERS as
// a-fragments for gemm2 (c-frag layout == a-frag layout per quadrant):
// no S smem round-trip, no S ldmatrix.  gemm2: O += Shi*Vhi + Shi*Vlo
// + Slo*Vhi with V stored transposed [d][s].
// Smem tiles: rows padded to 72 bf16 (144B) -> ldmatrix phases conflict-free.
// 2 barriers per s-tile.  72 KB smem, 2 CTAs/SM.
// ---------------------------------------------------------------------------
#define LQ 72

__global__ __launch_bounds__(256, 2) void attn_kernel(float* __restrict__ out) {
    extern __shared__ __nv_bfloat16 sbm[];
    __nv_bfloat16* Qhi = sbm;             // 128*72
    __nv_bfloat16* Qlo = sbm + 9216;      // 128*72
    __nv_bfloat16* Khi = sbm + 18432;     // 64*72  [s][d]
    __nv_bfloat16* Klo = sbm + 23040;
    __nv_bfloat16* Vhi = sbm + 27648;     // 64*72  [d][s] (transposed)
    __nv_bfloat16* Vlo = sbm + 32256;

    const int tq  = 5 - (blockIdx.x >> 7);   // heavy blocks first
    const int bh  = blockIdx.x & 127;
    const int tid = threadIdx.x;
    const int wid = tid >> 5;                // 0..7 -> rows wid*16..+15
    const int lane = tid & 31;

    const float* __restrict__ qb = g_q + bh * (TT * DHH) + tq * 128 * DHH;
    const float* __restrict__ kb = g_k + bh * (TT * DHH);
    const float* __restrict__ vb = g_v + bh * (TT * DHH);

    // ---- Q: load + rope + split hi/lo -> smem ----
    #pragma unroll
    for (int it = 0; it < 8; it++) {
        int v = tid + it * 256;
        int r = v >> 4, c4 = (v & 15) * 4;
        int t = tq * 128 + r;
        float4 xq = *(const float4*)(qb + r * DHH + c4);
        float4 xp = *(const float4*)(qb + r * DHH + (c4 ^ 32));
        float4 cc = *(const float4*)(g_cos + t * DHH + c4);
        float4 sn = *(const float4*)(g_sin + t * DHH + c4);
        float sgn = (c4 < 32) ? -1.0f : 1.0f;
        float o[4];
        o[0] = xq.x * cc.x + sgn * xp.x * sn.x;
        o[1] = xq.y * cc.y + sgn * xp.y * sn.y;
        o[2] = xq.z * cc.z + sgn * xp.z * sn.z;
        o[3] = xq.w * cc.w + sgn * xp.w * sn.w;
        union { __nv_bfloat16 b[4]; ull u; } H, L;
        #pragma unroll
        for (int j = 0; j < 4; j++) {
            H.b[j] = __float2bfloat16(o[j]);
            L.b[j] = __float2bfloat16(o[j] - __bfloat162float(H.b[j]));
        }
        *(ull*)&Qhi[r * LQ + c4] = H.u;
        *(ull*)&Qlo[r * LQ + c4] = L.u;
    }

    float oacc[8][4];
    #pragma unroll
    for (int nb = 0; nb < 8; nb++)
        #pragma unroll
        for (int q = 0; q < 4; q++)
            oacc[nb][q] = 0.0f;

    const int ks  = tid & 63;
    const int kd4 = (tid >> 6) * 4;

    // fragment element offsets (validated bit-roles from the passing GEMM)
    const int aQe = (wid*16 + (lane & 7) + ((lane >> 3) & 1) * 8) * LQ + (lane >> 4) * 8;
    const int bKe = ((lane & 7) + ((lane >> 4) & 1) * 8) * LQ + ((lane >> 3) & 1) * 8;

    const unsigned uQhi = s2u(Qhi), uQlo = s2u(Qlo);
    const unsigned uKhi = s2u(Khi), uKlo = s2u(Klo);
    const unsigned uVhi = s2u(Vhi), uVlo = s2u(Vlo);

    const int nsb = 2 * tq + 1;
    #pragma unroll 1
    for (int sbi = 0; sbi <= nsb; sbi++) {
        const float* __restrict__ kt = kb + sbi * 64 * DHH;
        const float* __restrict__ vt = vb + sbi * 64 * DHH;

        __syncthreads();   // prev tile reads done (also covers Q stores, iter 0)

        // ---- K: load + rope + split -> Khi/Klo [s][d] ----
        #pragma unroll
        for (int it = 0; it < 4; it++) {
            int d4 = kd4 + it * 16;
            float4 xk = *(const float4*)(kt + ks * DHH + d4);
            float4 xp = *(const float4*)(kt + ks * DHH + (d4 ^ 32));
            int t = sbi * 64 + ks;
            float4 cc = *(const float4*)(g_cos + t * DHH + d4);
            float4 sn = *(const float4*)(g_sin + t * DHH + d4);
            float sgn = (d4 < 32) ? -1.0f : 1.0f;
            float o[4];
            o[0] = xk.x * cc.x + sgn * xp.x * sn.x;
            o[1] = xk.y * cc.y + sgn * xp.y * sn.y;
            o[2] = xk.z * cc.z + sgn * xp.z * sn.z;
            o[3] = xk.w * cc.w + sgn * xp.w * sn.w;
            union { __nv_bfloat16 b[4]; ull u; } H, L;
            #pragma unroll
            for (int j = 0; j < 4; j++) {
                H.b[j] = __float2bfloat16(o[j]);
                L.b[j] = __float2bfloat16(o[j] - __bfloat162float(H.b[j]));
            }
            *(ull*)&Khi[ks * LQ + d4] = H.u;
            *(ull*)&Klo[ks * LQ + d4] = L.u;
        }
        // ---- V: load + split + transpose -> Vhi/Vlo [d][s] ----
        #pragma unroll
        for (int it = 0; it < 4; it++) {
            int d4 = kd4 + it * 16;
            float4 vv = *(const float4*)(vt + ks * DHH + d4);
            float o[4] = {vv.x, vv.y, vv.z, vv.w};
            #pragma unroll
            for (int j = 0; j < 4; j++) {
                __nv_bfloat16 h = __float2bfloat16(o[j]);
                Vhi[(d4 + j) * LQ + ks] = h;
                Vlo[(d4 + j) * LQ + ks] =
                    __float2bfloat16(o[j] - __bfloat162float(h));
            }
        }
        __syncthreads();

        // per-warp exact skip: all 16 rows fully masked?
        if ((tq * 128 + wid * 16 + 15) >= sbi * 64) {
            // ---- gemm1: S = Qhi*Khi + Qhi*Klo + Qlo*Khi ----
            float c[8][4];
            #pragma unroll
            for (int nb = 0; nb < 8; nb++)
                #pragma unroll
                for (int q = 0; q < 4; q++)
                    c[nb][q] = 0.0f;

            #pragma unroll
            for (int kk = 0; kk < 4; kk++) {
                unsigned aH[4], aL[4];
                ldmx4(aH[0], aH[1], aH[2], aH[3], uQhi + (aQe + kk*16) * 2);
                ldmx4(aL[0], aL[1], aL[2], aL[3], uQlo + (aQe + kk*16) * 2);
                #pragma unroll
                for (int nb = 0; nb < 4; nb++) {
                    const unsigned boff = (bKe + nb*16*LQ + kk*16) * 2;
                    unsigned b0, b1, b2, b3;
                    ldmx4(b0, b1, b2, b3, uKhi + boff);
                    mma16816(c[2*nb],     aH, b0, b1);
                    mma16816(c[2*nb + 1], aH, b2, b3);
                    mma16816(c[2*nb],     aL, b0, b1);
                    mma16816(c[2*nb + 1], aL, b2, b3);
                    ldmx4(b0, b1, b2, b3, uKlo + boff);
                    mma16816(c[2*nb],     aH, b0, b1);
                    mma16816(c[2*nb + 1], aH, b2, b3);
                }
            }

            // ---- causal mask on c-frags (diagonal band only) ----
            if (sbi >= 2 * tq) {
                const int row0 = tq * 128 + wid * 16 + (lane >> 2);
                const int col0 = sbi * 64 + (lane & 3) * 2;
                #pragma unroll
                for (int nb = 0; nb < 8; nb++)
                    #pragma unroll
                    for (int q = 0; q < 4; q++) {
                        int row = row0 + (q >> 1) * 8;
                        int col = col0 + nb * 8 + (q & 1);
                        if (col > row) c[nb][q] = 0.0f;
                    }
            }

            // ---- split S hi/lo and repack as gemm2 a-fragments (registers) --
            unsigned sh[8][2], sl[8][2];
            #pragma unroll
            for (int nb = 0; nb < 8; nb++) {
                float h0 = bfrt(c[nb][0]), h1 = bfrt(c[nb][1]);
                float h2 = bfrt(c[nb][2]), h3 = bfrt(c[nb][3]);
                sh[nb][0] = pkbf(c[nb][0], c[nb][1]);
                sh[nb][1] = pkbf(c[nb][2], c[nb][3]);
                sl[nb][0] = pkbf(c[nb][0] - h0, c[nb][1] - h1);
                sl[nb][1] = pkbf(c[nb][2] - h2, c[nb][3] - h3);
            }

            // ---- gemm2: O += Shi*Vhi + Shi*Vlo + Slo*Vhi ----
            #pragma unroll
            for (int j = 0; j < 4; j++) {
                unsigned aS[4]  = { sh[2*j][0], sh[2*j][1],
                                    sh[2*j + 1][0], sh[2*j + 1][1] };
                unsigned aSl[4] = { sl[2*j][0], sl[2*j][1],
                                    sl[2*j + 1][0], sl[2*j + 1][1] };
                #pragma unroll
                for (int nb = 0; nb < 4; nb++) {
                    const unsigned boff = (bKe + nb*16*LQ + j*16) * 2;
                    unsigned b0, b1, b2, b3;
                    ldmx4(b0, b1, b2, b3, uVhi + boff);
                    mma16816(oacc[2*nb],     aS,  b0, b1);
                    mma16816(oacc[2*nb + 1], aS,  b2, b3);
                    mma16816(oacc[2*nb],     aSl, b0, b1);
                    mma16816(oacc[2*nb + 1], aSl, b2, b3);
                    ldmx4(b0, b1, b2, b3, uVlo + boff);
                    mma16816(oacc[2*nb],     aS,  b0, b1);
                    mma16816(oacc[2*nb + 1], aS,  b2, b3);
                }
            }
        }
    }

    // ---- epilogue: out[b][t][h*64 + d] ----
    const int b_ = bh >> 4;
    const int h_ = bh & 15;
    const int r0 = tq * 128 + wid * 16 + (lane >> 2);
    const int d0 = (lane & 3) * 2;
    #pragma unroll
    for (int nb = 0; nb < 8; nb++)
        #pragma unroll
        for (int hf = 0; hf < 2; hf++) {
            int t_ = r0 + hf * 8;
            int d  = nb * 8 + d0;
            float2 ov;
            ov.x = oacc[nb][2*hf + 0];
            ov.y = oacc[nb][2*hf + 1];
            *(float2*)(out + (b_ * TT + t_) * DD + h_ * DHH + d) = ov;
        }
}

// ---------------------------------------------------------------------------
extern "C" void kernel_launch(void* const* d_in, const int* in_sizes, int n_in,
                              void* d_out, int out_size) {
    const float* x    = (const float*)d_in[0];
    const float* W    = (const float*)d_in[1];
    const float* bias = (const float*)d_in[2];
    float* out = (float*)d_out;

    cudaFuncSetAttribute(attn_kernel,
                         cudaFuncAttributeMaxDynamicSharedMemorySize, 73728);

    build_rope_kernel<<<TT, 32>>>();
    const int splitBlocks = ((BT*DD + N3*DD) / 4 + 255) / 256;
    split_kernel<<<splitBlocks, 256>>>(x, W);
    hmma_gemm_kernel<<<dim3(N3/128, BT/128), 256>>>(bias);
    attn_kernel<<<TT/128 * BB*HH, 256, 73728>>>(out);
}